// round 15
// baseline (speedup 1.0000x reference)
#include <cuda_runtime.h>

typedef unsigned long long ull;

#define MD 100
#define HD 512
#define NP 10000
#define MN 51200

// ---------------- device scratch ----------------
__device__ __align__(16) float g_child0[MD*HD];
__device__ __align__(16) float g_child1[MD*HD];
__device__ __align__(16) float g_child2[MD*HD];
__device__ __align__(16) float g_A[MD*HD];
__device__ __align__(16) float g_B[MD*HD];
__device__ __align__(16) float g_Ai[MD*HD];
__device__ __align__(16) float g_Bj[MD*HD];
__device__ __align__(16) float g_Ce0[NP*HD];
__device__ __align__(16) float g_Ce1[NP*HD];
__device__ __align__(16) float g_gpart[4*MN];
__device__ __align__(16) float g_part[16*MN];
__device__ __align__(16) float g_partS[4*5700];
__device__ __align__(16) float2 g_ELs[NP*HD];     // pre-split edge latents {hi,lo}
__device__ __align__(16) float2 g_Ws0[HD*HD];     // pre-split We0
__device__ __align__(16) float2 g_Ws1[HD*HD];     // pre-split We1
__device__ int   g_nodeok[MD];
__device__ int   g_pairlist[NP];
__device__ int   g_paircnt;

__device__ __forceinline__ ull ffma2(ull a, ull b, ull c){
    ull d;
    asm("fma.rn.f32x2 %0, %1, %2, %3;" : "=l"(d) : "l"(a), "l"(b), "l"(c));
    return d;
}
__device__ __forceinline__ ull dup2(float v){
    unsigned u = __float_as_uint(v);
    return ((ull)u << 32) | (ull)u;
}
// truncating tf32 split: hi/lo both valid tf32 bit patterns, hi+lo ~ v (err ~2^-22)
__device__ __forceinline__ float2 tfsplit(float v){
    float hi = __uint_as_float(__float_as_uint(v) & 0xFFFFE000u);
    float lo = v - hi;
    lo = __uint_as_float(__float_as_uint(lo) & 0xFFFFE000u);
    return make_float2(hi, lo);
}
__device__ __forceinline__ void mma_tf32(float4& d, unsigned a0, unsigned a1,
                                         unsigned a2, unsigned a3,
                                         unsigned b0, unsigned b1){
    asm volatile("mma.sync.aligned.m16n8k8.row.col.f32.tf32.tf32.f32 "
                 "{%0,%1,%2,%3}, {%4,%5,%6,%7}, {%8,%9}, {%0,%1,%2,%3};"
                 : "+f"(d.x), "+f"(d.y), "+f"(d.z), "+f"(d.w)
                 : "r"(a0), "r"(a1), "r"(a2), "r"(a3), "r"(b0), "r"(b1));
}
__device__ __forceinline__ float* sel_buf(int code){
    switch (code){
        case 0: return g_A;      case 1: return g_B;
        case 2: return g_Ai;     case 3: return g_Bj;
        case 4: return g_part;   case 5: return g_child0;
        case 6: return g_child1; default: return g_child2;
    }
}
__device__ __forceinline__ float fetchA(int code, int m, int k){
    if (code == 9){   // virtual concat [child0|child1|child2]
        int q = k >> 9, kk = k & 511;
        const float* s = (q==0) ? g_child0 : (q==1) ? g_child1 : g_child2;
        return s[m*HD + kk];
    }
    return sel_buf(code)[m*HD + k];
}

// ---------------- pre-split We0/We1. grid (256,2), 256 thr ----------------
__global__ void k_wsplit(const float* __restrict__ We0, const float* __restrict__ We1){
    const int q = blockIdx.x*256 + threadIdx.x;    // quad 0..65535
    const float* W = blockIdx.y ? We1 : We0;
    float2* D      = blockIdx.y ? g_Ws1 : g_Ws0;
    float4 v = ((const float4*)W)[q];
    float2 d0 = tfsplit(v.x), d1 = tfsplit(v.y), d2 = tfsplit(v.z), d3 = tfsplit(v.w);
    float4* o = (float4*)&D[q*4];
    o[0] = make_float4(d0.x, d0.y, d1.x, d1.y);
    o[1] = make_float4(d2.x, d2.y, d3.x, d3.y);
}

// ---------------- parent GEMV: float4, split-K. grid (50,4), 256 thr ----------------
__global__ void k_gemv_part(const float* __restrict__ pf, const float* __restrict__ Wp){
    __shared__ float pfs[128];
    const int z = blockIdx.y;
    const int c4 = blockIdx.x*256 + threadIdx.x;
    if (threadIdx.x < 128) pfs[threadIdx.x] = pf[z*128 + threadIdx.x];
    __syncthreads();
    const float4* w = (const float4*)Wp + (long long)(z*128)*12800 + c4;
    float4 a = make_float4(0.f,0.f,0.f,0.f);
    #pragma unroll 8
    for (int k=0; k<128; k++){
        float4 wv = w[(long long)k*12800];
        float s = pfs[k];
        a.x += s*wv.x; a.y += s*wv.y; a.z += s*wv.z; a.w += s*wv.w;
    }
    ((float4*)g_gpart)[z*12800 + c4] = a;
}

// finisher + exists logits fused. grid 100, 128 thr.
__global__ void k_gemv_fin(const float* __restrict__ bp, const float* __restrict__ Wx,
                           const float* __restrict__ bx, float* __restrict__ out_ex){
    __shared__ float red[4];
    const int m = blockIdx.x, t = threadIdx.x;
    const int c4 = m*128 + t;
    const float4* gp = (const float4*)g_gpart;
    float4 s0 = gp[c4], s1 = gp[12800+c4], s2 = gp[2*12800+c4], s3 = gp[3*12800+c4];
    float4 b  = ((const float4*)bp)[c4];
    float4 v;
    v.x = fmaxf(s0.x+s1.x+s2.x+s3.x+b.x, 0.f);
    v.y = fmaxf(s0.y+s1.y+s2.y+s3.y+b.y, 0.f);
    v.z = fmaxf(s0.z+s1.z+s2.z+s3.z+b.z, 0.f);
    v.w = fmaxf(s0.w+s1.w+s2.w+s3.w+b.w, 0.f);
    ((float4*)g_child0)[c4] = v;
    float4 wx = ((const float4*)Wx)[t];
    float p = v.x*wx.x + v.y*wx.y + v.z*wx.z + v.w*wx.w;
    #pragma unroll
    for (int o=16; o; o>>=1) p += __shfl_xor_sync(~0u, p, o);
    if ((t & 31) == 0) red[t>>5] = p;
    __syncthreads();
    if (t == 0){
        float vv = red[0]+red[1]+red[2]+red[3] + bx[0];
        out_ex[m]   = vv;
        g_nodeok[m] = (vv > 0.f) ? 1 : 0;
        if (m == 0) g_paircnt = 0;
    }
}

// ---------------- split-K multi-job GEMM partials, pipelined ----------------
__global__ void k_gp(int acodes, int Klen, int KS,
                     const float* __restrict__ B0, const float* __restrict__ B1,
                     const float* __restrict__ B2, const float* __restrict__ B3){
    __shared__ ull   As2[16*33];
    __shared__ float Bs[16*68];
    const int KSL = Klen / KS;
    const int job = blockIdx.z / KS, sl = blockIdx.z % KS;
    const int Acode = (acodes >> (8*job)) & 255;
    const float* B = (job==0)?B0:(job==1)?B1:(job==2)?B2:B3;
    const int kb = sl*KSL;
    const int n0 = blockIdx.x*64, m0 = blockIdx.y*32;
    const int t = threadIdx.x, tr = t>>4, tc = t&15;
    const int ar0 = t>>4, ak = t&15, ar1 = ar0+16;
    const int bn = t&63, bk0 = t>>6;
    const int gm0 = m0+ar0, gm1 = m0+ar1;
    float pa0, pa1, pb0, pb1, pb2, pb3;
    {
        int k = kb + ak;
        pa0 = (gm0 < MD) ? fetchA(Acode, gm0, k) : 0.f;
        pa1 = (gm1 < MD) ? fetchA(Acode, gm1, k) : 0.f;
        int kB = kb + bk0;
        pb0 = B[(kB   )*HD + n0+bn]; pb1 = B[(kB+4 )*HD + n0+bn];
        pb2 = B[(kB+8 )*HD + n0+bn]; pb3 = B[(kB+12)*HD + n0+bn];
    }
    ull acc[2][2] = {};
    const int nkt = KSL/16;
    for (int kt=0; kt<nkt; kt++){
        As2[ak*33 + ar0] = dup2(pa0);
        As2[ak*33 + ar1] = dup2(pa1);
        Bs[(bk0   )*68 + bn] = pb0;
        Bs[(bk0+4 )*68 + bn] = pb1;
        Bs[(bk0+8 )*68 + bn] = pb2;
        Bs[(bk0+12)*68 + bn] = pb3;
        __syncthreads();
        if (kt+1 < nkt){
            int k = kb + (kt+1)*16 + ak;
            pa0 = (gm0 < MD) ? fetchA(Acode, gm0, k) : 0.f;
            pa1 = (gm1 < MD) ? fetchA(Acode, gm1, k) : 0.f;
            int kB = kb + (kt+1)*16 + bk0;
            pb0 = B[(kB   )*HD + n0+bn]; pb1 = B[(kB+4 )*HD + n0+bn];
            pb2 = B[(kB+8 )*HD + n0+bn]; pb3 = B[(kB+12)*HD + n0+bn];
        }
        #pragma unroll
        for (int k=0; k<16; k++){
            ull a0 = As2[k*33+tr], a1 = As2[k*33+tr+16];
            float4 bf = *(const float4*)&Bs[k*68 + tc*4];
            ull b0 = ((const ull*)&bf)[0], b1 = ((const ull*)&bf)[1];
            acc[0][0]=ffma2(a0,b0,acc[0][0]); acc[0][1]=ffma2(a0,b1,acc[0][1]);
            acc[1][0]=ffma2(a1,b0,acc[1][0]); acc[1][1]=ffma2(a1,b1,acc[1][1]);
        }
        __syncthreads();
    }
    float* P = g_part + (size_t)blockIdx.z*MN;
    #pragma unroll
    for (int rr=0; rr<2; rr++){
        int gm = m0 + tr + rr*16;
        if (gm < MD){
            ull* cp = (ull*)(P + gm*HD + n0 + tc*4);
            cp[0] = acc[rr][0]; cp[1] = acc[rr][1];
        }
    }
}

// sum S slices per job (float4)
__global__ void k_red(int S, int njobs, int d0, int d1, int d2, int d3){
    int i4 = blockIdx.x*256 + threadIdx.x;
    if (i4 >= njobs*12800) return;
    int job = i4 / 12800, e4 = i4 - job*12800;
    const float4* P = (const float4*)g_part;
    float4 s = make_float4(0.f,0.f,0.f,0.f);
    for (int z=0; z<S; z++){
        float4 v = P[(size_t)(job*S+z)*12800 + e4];
        s.x+=v.x; s.y+=v.y; s.z+=v.z; s.w+=v.w;
    }
    int dc = (job==0)?d0:(job==1)?d1:(job==2)?d2:d3;
    ((float4*)sel_buf(dc))[e4] = s;
}

// ---------------- edge logits + pair compaction + EL split. grid (100,13), 256 thr ----------------
__global__ void k_el(const float* __restrict__ bel, const float* __restrict__ Wee,
                     const float* __restrict__ bee, float* __restrict__ out_lg){
    __shared__ float sWee[4*HD];
    __shared__ float sbel[HD];
    const int t = threadIdx.x;
    #pragma unroll
    for (int q=0; q<8; q++) sWee[t + q*256] = Wee[t + q*256];
    sbel[t] = bel[t]; sbel[t+256] = bel[t+256];
    __syncthreads();
    const int i = blockIdx.x;
    const int w = t >> 5, lane = t & 31;
    const int j = blockIdx.y*8 + w;
    if (j >= MD) return;
    const float* Ar = g_A + i*HD;
    const float* Br = g_B + j*HD;
    const int p = i*MD + j;
    const bool okp = g_nodeok[i] && g_nodeok[j];
    float2* eld = g_ELs + (size_t)p*HD;
    float p0=0.f, p1=0.f, p2=0.f, p3=0.f;
    #pragma unroll
    for (int s=0; s<16; s++){
        int h = lane + s*32;
        float v = fmaxf(Ar[h] + Br[h] + sbel[h], 0.f);
        if (okp) eld[h] = tfsplit(v);
        p0 += v*sWee[h]; p1 += v*sWee[HD+h]; p2 += v*sWee[2*HD+h]; p3 += v*sWee[3*HD+h];
    }
    #pragma unroll
    for (int o=16; o; o>>=1){
        p0 += __shfl_xor_sync(~0u, p0, o);
        p1 += __shfl_xor_sync(~0u, p1, o);
        p2 += __shfl_xor_sync(~0u, p2, o);
        p3 += __shfl_xor_sync(~0u, p3, o);
    }
    if (lane == 0){
        p0 += bee[0]; p1 += bee[1]; p2 += bee[2]; p3 += bee[3];
        *(float4*)(out_lg + p*4) = make_float4(p0, p1, p2, p3);
        if (okp && (p0>0.f || p1>0.f || p2>0.f || p3>0.f)){
            int pos = atomicAdd(&g_paircnt, 1);
            g_pairlist[pos] = p;
        }
    }
}

// ---------------- gathered edge GEMM via TF32 tensor cores (3xTF32, pre-split operands) ----------------
// grid (8,157), 256 thr = 8 warps. Tile 64 pairs x 64 cols, BOTH iterations.
// Loaders are pure LDG.128/STS of precomputed {hi,lo}; zero arithmetic in the hot loop.
__global__ void k_ce(){
    __shared__ int pp[64];
    __shared__ __align__(16) float2 As [16*68];   // [k][row]
    __shared__ __align__(16) float2 Bs0[16*68];   // [k][n]
    __shared__ __align__(16) float2 Bs1[16*68];
    const int cnt = g_paircnt;
    const int m0  = blockIdx.y*64;
    if (m0 >= cnt) return;
    const int n0 = blockIdx.x*64;
    const int t = threadIdx.x;
    if (t < 64){
        pp[t] = (m0 + t < cnt) ? g_pairlist[m0 + t] : g_pairlist[m0];
    }
    __syncthreads();
    // loader mappings
    const int lr  = t & 63, lk4 = (t >> 6)*4;     // A: row, 4 consecutive k
    const int bk  = t >> 4, bn4 = (t & 15)*4;     // B: k-row, 4 consecutive n
    const float2* Asrc = g_ELs + (size_t)pp[lr]*HD;
    // warp/mma mappings
    const int w = t >> 5, lane = t & 31;
    const int mw = w & 1, nw = w >> 1;
    const int g  = lane >> 2, ctg = lane & 3;
    float4 a01, a23, b0a, b0b, b1a, b1b;
    a01 = *(const float4*)&Asrc[lk4];
    a23 = *(const float4*)&Asrc[lk4 + 2];
    b0a = *(const float4*)&g_Ws0[bk*HD + n0 + bn4];
    b0b = *(const float4*)&g_Ws0[bk*HD + n0 + bn4 + 2];
    b1a = *(const float4*)&g_Ws1[bk*HD + n0 + bn4];
    b1b = *(const float4*)&g_Ws1[bk*HD + n0 + bn4 + 2];
    float4 acc[2][2][2];   // [iter][mt][nt]
    #pragma unroll
    for (int i1=0;i1<2;i1++)
        #pragma unroll
        for (int i2=0;i2<2;i2++)
            #pragma unroll
            for (int i3=0;i3<2;i3++) acc[i1][i2][i3] = make_float4(0.f,0.f,0.f,0.f);
    for (int kt=0; kt<32; kt++){
        As[(lk4  )*68 + lr] = make_float2(a01.x, a01.y);
        As[(lk4+1)*68 + lr] = make_float2(a01.z, a01.w);
        As[(lk4+2)*68 + lr] = make_float2(a23.x, a23.y);
        As[(lk4+3)*68 + lr] = make_float2(a23.z, a23.w);
        *(float4*)&Bs0[bk*68 + bn4]     = b0a;
        *(float4*)&Bs0[bk*68 + bn4 + 2] = b0b;
        *(float4*)&Bs1[bk*68 + bn4]     = b1a;
        *(float4*)&Bs1[bk*68 + bn4 + 2] = b1b;
        __syncthreads();
        if (kt+1 < 32){
            int ko = (kt+1)*16;
            a01 = *(const float4*)&Asrc[ko + lk4];
            a23 = *(const float4*)&Asrc[ko + lk4 + 2];
            b0a = *(const float4*)&g_Ws0[(ko + bk)*HD + n0 + bn4];
            b0b = *(const float4*)&g_Ws0[(ko + bk)*HD + n0 + bn4 + 2];
            b1a = *(const float4*)&g_Ws1[(ko + bk)*HD + n0 + bn4];
            b1b = *(const float4*)&g_Ws1[(ko + bk)*HD + n0 + bn4 + 2];
        }
        #pragma unroll
        for (int ks=0; ks<16; ks+=8){
            float2 af[2][4];
            #pragma unroll
            for (int mt=0; mt<2; mt++){
                int mo = mw*32 + mt*16;
                af[mt][0] = As[(ks+ctg  )*68 + mo + g];
                af[mt][1] = As[(ks+ctg  )*68 + mo + g + 8];
                af[mt][2] = As[(ks+ctg+4)*68 + mo + g];
                af[mt][3] = As[(ks+ctg+4)*68 + mo + g + 8];
            }
            #pragma unroll
            for (int it=0; it<2; it++){
                const float2* Bsm = it ? Bs1 : Bs0;
                #pragma unroll
                for (int nt=0; nt<2; nt++){
                    int no = nw*16 + nt*8;
                    float2 bf0 = Bsm[(ks+ctg  )*68 + no + g];
                    float2 bf1 = Bsm[(ks+ctg+4)*68 + no + g];
                    unsigned bh0 = __float_as_uint(bf0.x), bh1 = __float_as_uint(bf1.x);
                    unsigned bl0 = __float_as_uint(bf0.y), bl1 = __float_as_uint(bf1.y);
                    #pragma unroll
                    for (int mt=0; mt<2; mt++){
                        unsigned ah0 = __float_as_uint(af[mt][0].x);
                        unsigned ah1 = __float_as_uint(af[mt][1].x);
                        unsigned ah2 = __float_as_uint(af[mt][2].x);
                        unsigned ah3 = __float_as_uint(af[mt][3].x);
                        unsigned al0 = __float_as_uint(af[mt][0].y);
                        unsigned al1 = __float_as_uint(af[mt][1].y);
                        unsigned al2 = __float_as_uint(af[mt][2].y);
                        unsigned al3 = __float_as_uint(af[mt][3].y);
                        float4& d = acc[it][mt][nt];
                        mma_tf32(d, ah0, ah1, ah2, ah3, bh0, bh1);   // hi*hi
                        mma_tf32(d, ah0, ah1, ah2, ah3, bl0, bl1);   // hi*lo
                        mma_tf32(d, al0, al1, al2, al3, bh0, bh1);   // lo*hi
                    }
                }
            }
        }
        __syncthreads();
    }
    #pragma unroll
    for (int it=0; it<2; it++){
        float* C = it ? g_Ce1 : g_Ce0;
        #pragma unroll
        for (int mt=0; mt<2; mt++){
            #pragma unroll
            for (int nt=0; nt<2; nt++){
                float4 d = acc[it][mt][nt];
                int rl0 = mw*32 + mt*16 + g;
                int col = n0 + nw*16 + nt*8 + ctg*2;
                if (m0 + rl0 < cnt){
                    float* p = C + pp[rl0]*HD + col;
                    p[0] = d.x; p[1] = d.y;
                }
                int rl1 = rl0 + 8;
                if (m0 + rl1 < cnt){
                    float* p = C + pp[rl1]*HD + col;
                    p[0] = d.z; p[1] = d.w;
                }
            }
        }
    }
}

// ---------------- message pass + scatter-sum. grid 100, 512 thr, 4-deep prefetch ----------------
__global__ void k_msg(int it, const float* __restrict__ lgg,
                      const float* __restrict__ Wt, const float* __restrict__ bne){
    __shared__ float lg[400];
    __shared__ int   jl[100];
    __shared__ int   njl;
    const float* childin  = it ? g_child1 : g_child0;
    float*       childout = it ? g_child2 : g_child1;
    const float* Ce       = it ? g_Ce1    : g_Ce0;
    const int i = blockIdx.x, h = threadIdx.x;
    if (h < 400) lg[h] = lgg[i*400 + h];
    __syncthreads();
    if (h == 0){
        int n = 0;
        if (g_nodeok[i]){
            for (int j=0; j<MD; j++){
                if (!g_nodeok[j]) continue;
                if (lg[j*4]>0.f || lg[j*4+1]>0.f || lg[j*4+2]>0.f || lg[j*4+3]>0.f) jl[n++] = j;
            }
        }
        njl = n;
    }
    __syncthreads();
    float cin = childin[i*HD + h];
    bool any = (g_paircnt > 0);
    float acc = 0.f;
    const int n = njl;
    float base_i = g_Ai[i*HD + h] + bne[h];
    float wt0 = Wt[h], wt1 = Wt[HD+h], wt2 = Wt[2*HD+h], wt3 = Wt[3*HD+h];
    const float* CeI = Ce + (long long)i*MD*HD;

    #define MSG_BODY(JB, CB, CC) { \
        float l0 = lg[(JB)*4], l1 = lg[(JB)*4+1], l2 = lg[(JB)*4+2], l3 = lg[(JB)*4+3]; \
        float base = base_i + (CB) + (CC); \
        if (l0 > 0.f) acc += fmaxf(fmaf(l0, wt0, base), 0.f); \
        if (l1 > 0.f) acc += fmaxf(fmaf(l1, wt1, base), 0.f); \
        if (l2 > 0.f) acc += fmaxf(fmaf(l2, wt2, base), 0.f); \
        if (l3 > 0.f) acc += fmaxf(fmaf(l3, wt3, base), 0.f); }

    float b0=0,b1=0,b2=0,b3=0,c0=0,c1=0,c2=0,c3=0;
    if (n > 0){ int j=jl[0]; b0=g_Bj[j*HD+h]; c0=CeI[j*HD+h]; }
    if (n > 1){ int j=jl[1]; b1=g_Bj[j*HD+h]; c1=CeI[j*HD+h]; }
    if (n > 2){ int j=jl[2]; b2=g_Bj[j*HD+h]; c2=CeI[j*HD+h]; }
    if (n > 3){ int j=jl[3]; b3=g_Bj[j*HD+h]; c3=CeI[j*HD+h]; }
    int q = 0;
    const int nq = n & ~3;
    for (; q < nq; q += 4){
        float tb0=b0, tc0=c0, tb1=b1, tc1=c1, tb2=b2, tc2=c2, tb3=b3, tc3=c3;
        if (q+4 < n){ int j=jl[q+4]; b0=g_Bj[j*HD+h]; c0=CeI[j*HD+h]; }
        if (q+5 < n){ int j=jl[q+5]; b1=g_Bj[j*HD+h]; c1=CeI[j*HD+h]; }
        if (q+6 < n){ int j=jl[q+6]; b2=g_Bj[j*HD+h]; c2=CeI[j*HD+h]; }
        if (q+7 < n){ int j=jl[q+7]; b3=g_Bj[j*HD+h]; c3=CeI[j*HD+h]; }
        MSG_BODY(jl[q  ], tb0, tc0);
        MSG_BODY(jl[q+1], tb1, tc1);
        MSG_BODY(jl[q+2], tb2, tc2);
        MSG_BODY(jl[q+3], tb3, tc3);
    }
    for (; q < n; q++){
        int j = jl[q];
        float cb = g_Bj[j*HD+h], cc = CeI[j*HD+h];
        MSG_BODY(j, cb, cc);
    }
    #undef MSG_BODY
    childout[i*HD + h] = any ? acc : cin;
}

// ---------------- heads partials with inline h-reduce. grid (9,4,4) ----------------
__device__ __forceinline__ float hval(int gm, int k, const float* __restrict__ bc){
    float s = 0.f;
    #pragma unroll
    for (int z=0; z<8; z++) s += g_part[(size_t)z*MN + gm*HD + k];
    return fmaxf(s + bc[k], 0.f);
}
__global__ void k_heads(const float* __restrict__ Wc2, const float* __restrict__ Ws,
                        const float* __restrict__ bc){
    __shared__ ull   As2[16*33];
    __shared__ float Bs[16*68];
    const bool semjob = (blockIdx.x == 8);
    const float* B = semjob ? Ws : Wc2;
    const int N   = semjob ? 57 : 512;
    const int n0  = semjob ? 0  : blockIdx.x*64;
    const int m0  = blockIdx.y*32;
    const int kb  = blockIdx.z*128;
    const int t = threadIdx.x, tr = t>>4, tc = t&15;
    const int ar0 = t>>4, ak = t&15, ar1 = ar0+16;
    const int bn = t&63, bk0 = t>>6;
    const int gm0 = m0+ar0, gm1 = m0+ar1;
    const bool bok = (n0 + bn) < N;
    float pa0, pa1, pb0, pb1, pb2, pb3;
    {
        int k = kb + ak;
        pa0 = (gm0 < MD) ? hval(gm0, k, bc) : 0.f;
        pa1 = (gm1 < MD) ? hval(gm1, k, bc) : 0.f;
        int kB = kb + bk0;
        pb0 = bok ? B[(kB   )*N + n0+bn] : 0.f;
        pb1 = bok ? B[(kB+4 )*N + n0+bn] : 0.f;
        pb2 = bok ? B[(kB+8 )*N + n0+bn] : 0.f;
        pb3 = bok ? B[(kB+12)*N + n0+bn] : 0.f;
    }
    ull acc[2][2] = {};
    for (int kt=0; kt<8; kt++){
        As2[ak*33 + ar0] = dup2(pa0);
        As2[ak*33 + ar1] = dup2(pa1);
        Bs[(bk0   )*68 + bn] = pb0;
        Bs[(bk0+4 )*68 + bn] = pb1;
        Bs[(bk0+8 )*68 + bn] = pb2;
        Bs[(bk0+12)*68 + bn] = pb3;
        __syncthreads();
        if (kt+1 < 8){
            int k = kb + (kt+1)*16 + ak;
            pa0 = (gm0 < MD) ? hval(gm0, k, bc) : 0.f;
            pa1 = (gm1 < MD) ? hval(gm1, k, bc) : 0.f;
            int kB = kb + (kt+1)*16 + bk0;
            pb0 = bok ? B[(kB   )*N + n0+bn] : 0.f;
            pb1 = bok ? B[(kB+4 )*N + n0+bn] : 0.f;
            pb2 = bok ? B[(kB+8 )*N + n0+bn] : 0.f;
            pb3 = bok ? B[(kB+12)*N + n0+bn] : 0.f;
        }
        #pragma unroll
        for (int k=0; k<16; k++){
            ull a0 = As2[k*33+tr], a1 = As2[k*33+tr+16];
            float4 bf = *(const float4*)&Bs[k*68 + tc*4];
            ull b0 = ((const ull*)&bf)[0], b1 = ((const ull*)&bf)[1];
            acc[0][0]=ffma2(a0,b0,acc[0][0]); acc[0][1]=ffma2(a0,b1,acc[0][1]);
            acc[1][0]=ffma2(a1,b0,acc[1][0]); acc[1][1]=ffma2(a1,b1,acc[1][1]);
        }
        __syncthreads();
    }
    const int sl = blockIdx.z;
    #pragma unroll
    for (int rr=0; rr<2; rr++){
        int gm = m0 + tr + rr*16;
        if (gm >= MD) continue;
        float r0 = __uint_as_float((unsigned)(acc[rr][0]      ));
        float r1 = __uint_as_float((unsigned)(acc[rr][0] >> 32));
        float r2 = __uint_as_float((unsigned)(acc[rr][1]      ));
        float r3 = __uint_as_float((unsigned)(acc[rr][1] >> 32));
        int gn = n0 + tc*4;
        if (!semjob){
            ull* cp = (ull*)(g_part + (size_t)(8+sl)*MN + gm*HD + gn);
            cp[0] = acc[rr][0]; cp[1] = acc[rr][1];
        } else {
            float* P = g_partS + sl*5700 + gm*57;
            if (gn   < 57) P[gn  ] = r0;
            if (gn+1 < 57) P[gn+1] = r1;
            if (gn+2 < 57) P[gn+2] = r2;
            if (gn+3 < 57) P[gn+3] = r3;
        }
    }
}

// final output reduce. blocks 0..49: child_out float4 (part slices 8..11), 50..72: sem scalar.
__global__ void k_out(const float* __restrict__ bc2, const float* __restrict__ bs,
                      float* __restrict__ out_co, float* __restrict__ out_sem){
    if (blockIdx.x < 50){
        int i4 = blockIdx.x*256 + threadIdx.x;
        const float4* P = (const float4*)g_part;
        float4 s = make_float4(0.f,0.f,0.f,0.f);
        #pragma unroll
        for (int z=0; z<4; z++){
            float4 v = P[(size_t)(8+z)*12800 + i4];
            s.x+=v.x; s.y+=v.y; s.z+=v.z; s.w+=v.w;
        }
        float4 b = ((const float4*)bc2)[i4 & 127];
        s.x = fmaxf(s.x+b.x,0.f); s.y = fmaxf(s.y+b.y,0.f);
        s.z = fmaxf(s.z+b.z,0.f); s.w = fmaxf(s.w+b.w,0.f);
        ((float4*)out_co)[i4] = s;
    } else {
        int e = (blockIdx.x-50)*256 + threadIdx.x;
        if (e >= 5700) return;
        float s = 0.f;
        #pragma unroll
        for (int z=0; z<4; z++) s += g_partS[z*5700 + e];
        out_sem[e] = s + bs[e % 57];
    }
}

// ---------------- launch: 14 kernels ----------------
extern "C" void kernel_launch(void* const* d_in, const int* in_sizes, int n_in,
                              void* d_out, int out_size){
    const float* pf  = (const float*)d_in[0];
    const float* Wp  = (const float*)d_in[1];
    const float* bp  = (const float*)d_in[2];
    const float* Wx  = (const float*)d_in[3];
    const float* bx  = (const float*)d_in[4];
    const float* Wel = (const float*)d_in[5];
    const float* bel = (const float*)d_in[6];
    const float* Wee = (const float*)d_in[7];
    const float* bee = (const float*)d_in[8];
    const float* Wne = (const float*)d_in[9];
    const float* bne = (const float*)d_in[10];
    const float* Wc  = (const float*)d_in[11];
    const float* bc  = (const float*)d_in[12];
    const float* Ws  = (const float*)d_in[13];
    const float* bs  = (const float*)d_in[14];
    const float* Wc2 = (const float*)d_in[15];
    const float* bc2 = (const float*)d_in[16];

    float* out     = (float*)d_out;
    float* out_co  = out;
    float* out_sem = out + 51200;
    float* out_ex  = out + 56900;
    float* out_lg  = out + 57000;

    // 0: pre-split We0/We1 (independent of everything else)
    k_wsplit<<<dim3(256,2),256>>>(Wne + 1024*512, Wne + (1540+1024)*512);
    k_gemv_part<<<dim3(50,4),256>>>(pf, Wp);
    k_gemv_fin<<<100,128>>>(bp, Wx, bx, out_ex);
    k_gp<<<dim3(8,4,16),256>>>(5 | (5<<8) | (5<<16) | (5<<24), 512, 4,
                               Wel, Wel + 512*512, Wne, Wne + 512*512);
    k_red<<<200,256>>>(4, 4, 0, 1, 2, 3);
    k_el<<<dim3(100,13),256>>>(bel, Wee, bee, out_lg);
    k_ce<<<dim3(8,157),256>>>();
    k_msg<<<100,512>>>(0, out_lg, Wne + 1536*512, bne);
    k_gp<<<dim3(8,4,8),256>>>(6 | (6<<8), 512, 4,
                              Wne + 1540*512, Wne + (1540+512)*512, Wne, Wne);
    k_red<<<100,256>>>(4, 2, 2, 3, 0, 0);
    k_msg<<<100,512>>>(1, out_lg, Wne + (1540+1536)*512, bne + 512);
    k_gp<<<dim3(8,4,8),256>>>(9, 1536, 8, Wc, Wc, Wc, Wc);
    k_heads<<<dim3(9,4,4),256>>>(Wc2, Ws, bc);
    k_out<<<73,256>>>(bc2, bs, out_co, out_sem);
}

// round 16
// speedup vs baseline: 1.2237x; 1.2237x over previous
#include <cuda_runtime.h>

typedef unsigned long long ull;

#define MD 100
#define HD 512
#define NP 10000
#define MN 51200

// ---------------- device scratch ----------------
__device__ __align__(16) float g_child0[MD*HD];
__device__ __align__(16) float g_child1[MD*HD];
__device__ __align__(16) float g_child2[MD*HD];
__device__ __align__(16) float g_A[MD*HD];
__device__ __align__(16) float g_B[MD*HD];
__device__ __align__(16) float g_Ai[MD*HD];
__device__ __align__(16) float g_Bj[MD*HD];
__device__ __align__(16) float g_Ce0[NP*HD];
__device__ __align__(16) float g_Ce1[NP*HD];
__device__ __align__(16) float g_gpart[4*MN];
__device__ __align__(16) float g_part[16*MN];
__device__ __align__(16) float g_partS[4*5700];
__device__ int   g_nodeok[MD];
__device__ int   g_pairlist[NP];
__device__ int   g_paircnt;

__device__ __forceinline__ ull ffma2(ull a, ull b, ull c){
    ull d;
    asm("fma.rn.f32x2 %0, %1, %2, %3;" : "=l"(d) : "l"(a), "l"(b), "l"(c));
    return d;
}
__device__ __forceinline__ ull dup2(float v){
    unsigned u = __float_as_uint(v);
    return ((ull)u << 32) | (ull)u;
}
// truncating tf32 split via mask (full-rate ALU; validated rel_err ~1.36e-6)
__device__ __forceinline__ float2 tfsplit(float v){
    float hi = __uint_as_float(__float_as_uint(v) & 0xFFFFE000u);
    float lo = v - hi;
    lo = __uint_as_float(__float_as_uint(lo) & 0xFFFFE000u);
    return make_float2(hi, lo);
}
__device__ __forceinline__ void mma_tf32(float4& d, unsigned a0, unsigned a1,
                                         unsigned a2, unsigned a3,
                                         unsigned b0, unsigned b1){
    asm volatile("mma.sync.aligned.m16n8k8.row.col.f32.tf32.tf32.f32 "
                 "{%0,%1,%2,%3}, {%4,%5,%6,%7}, {%8,%9}, {%0,%1,%2,%3};"
                 : "+f"(d.x), "+f"(d.y), "+f"(d.z), "+f"(d.w)
                 : "r"(a0), "r"(a1), "r"(a2), "r"(a3), "r"(b0), "r"(b1));
}
__device__ __forceinline__ float* sel_buf(int code){
    switch (code){
        case 0: return g_A;      case 1: return g_B;
        case 2: return g_Ai;     case 3: return g_Bj;
        case 4: return g_part;   case 5: return g_child0;
        case 6: return g_child1; default: return g_child2;
    }
}
__device__ __forceinline__ float fetchA(int code, int m, int k){
    if (code == 9){   // virtual concat [child0|child1|child2]
        int q = k >> 9, kk = k & 511;
        const float* s = (q==0) ? g_child0 : (q==1) ? g_child1 : g_child2;
        return s[m*HD + kk];
    }
    return sel_buf(code)[m*HD + k];
}

// ---------------- parent GEMV: float4, split-K. grid (50,4), 256 thr ----------------
__global__ void k_gemv_part(const float* __restrict__ pf, const float* __restrict__ Wp){
    __shared__ float pfs[128];
    const int z = blockIdx.y;
    const int c4 = blockIdx.x*256 + threadIdx.x;
    if (threadIdx.x < 128) pfs[threadIdx.x] = pf[z*128 + threadIdx.x];
    __syncthreads();
    const float4* w = (const float4*)Wp + (long long)(z*128)*12800 + c4;
    float4 a = make_float4(0.f,0.f,0.f,0.f);
    #pragma unroll 8
    for (int k=0; k<128; k++){
        float4 wv = w[(long long)k*12800];
        float s = pfs[k];
        a.x += s*wv.x; a.y += s*wv.y; a.z += s*wv.z; a.w += s*wv.w;
    }
    ((float4*)g_gpart)[z*12800 + c4] = a;
}

// finisher + exists logits fused. grid 100, 128 thr.
__global__ void k_gemv_fin(const float* __restrict__ bp, const float* __restrict__ Wx,
                           const float* __restrict__ bx, float* __restrict__ out_ex){
    __shared__ float red[4];
    const int m = blockIdx.x, t = threadIdx.x;
    const int c4 = m*128 + t;
    const float4* gp = (const float4*)g_gpart;
    float4 s0 = gp[c4], s1 = gp[12800+c4], s2 = gp[2*12800+c4], s3 = gp[3*12800+c4];
    float4 b  = ((const float4*)bp)[c4];
    float4 v;
    v.x = fmaxf(s0.x+s1.x+s2.x+s3.x+b.x, 0.f);
    v.y = fmaxf(s0.y+s1.y+s2.y+s3.y+b.y, 0.f);
    v.z = fmaxf(s0.z+s1.z+s2.z+s3.z+b.z, 0.f);
    v.w = fmaxf(s0.w+s1.w+s2.w+s3.w+b.w, 0.f);
    ((float4*)g_child0)[c4] = v;
    float4 wx = ((const float4*)Wx)[t];
    float p = v.x*wx.x + v.y*wx.y + v.z*wx.z + v.w*wx.w;
    #pragma unroll
    for (int o=16; o; o>>=1) p += __shfl_xor_sync(~0u, p, o);
    if ((t & 31) == 0) red[t>>5] = p;
    __syncthreads();
    if (t == 0){
        float vv = red[0]+red[1]+red[2]+red[3] + bx[0];
        out_ex[m]   = vv;
        g_nodeok[m] = (vv > 0.f) ? 1 : 0;
        if (m == 0) g_paircnt = 0;
    }
}

// ---------------- split-K multi-job GEMM partials, pipelined ----------------
__global__ void k_gp(int acodes, int Klen, int KS,
                     const float* __restrict__ B0, const float* __restrict__ B1,
                     const float* __restrict__ B2, const float* __restrict__ B3){
    __shared__ ull   As2[16*33];
    __shared__ float Bs[16*68];
    const int KSL = Klen / KS;
    const int job = blockIdx.z / KS, sl = blockIdx.z % KS;
    const int Acode = (acodes >> (8*job)) & 255;
    const float* B = (job==0)?B0:(job==1)?B1:(job==2)?B2:B3;
    const int kb = sl*KSL;
    const int n0 = blockIdx.x*64, m0 = blockIdx.y*32;
    const int t = threadIdx.x, tr = t>>4, tc = t&15;
    const int ar0 = t>>4, ak = t&15, ar1 = ar0+16;
    const int bn = t&63, bk0 = t>>6;
    const int gm0 = m0+ar0, gm1 = m0+ar1;
    float pa0, pa1, pb0, pb1, pb2, pb3;
    {
        int k = kb + ak;
        pa0 = (gm0 < MD) ? fetchA(Acode, gm0, k) : 0.f;
        pa1 = (gm1 < MD) ? fetchA(Acode, gm1, k) : 0.f;
        int kB = kb + bk0;
        pb0 = B[(kB   )*HD + n0+bn]; pb1 = B[(kB+4 )*HD + n0+bn];
        pb2 = B[(kB+8 )*HD + n0+bn]; pb3 = B[(kB+12)*HD + n0+bn];
    }
    ull acc[2][2] = {};
    const int nkt = KSL/16;
    for (int kt=0; kt<nkt; kt++){
        As2[ak*33 + ar0] = dup2(pa0);
        As2[ak*33 + ar1] = dup2(pa1);
        Bs[(bk0   )*68 + bn] = pb0;
        Bs[(bk0+4 )*68 + bn] = pb1;
        Bs[(bk0+8 )*68 + bn] = pb2;
        Bs[(bk0+12)*68 + bn] = pb3;
        __syncthreads();
        if (kt+1 < nkt){
            int k = kb + (kt+1)*16 + ak;
            pa0 = (gm0 < MD) ? fetchA(Acode, gm0, k) : 0.f;
            pa1 = (gm1 < MD) ? fetchA(Acode, gm1, k) : 0.f;
            int kB = kb + (kt+1)*16 + bk0;
            pb0 = B[(kB   )*HD + n0+bn]; pb1 = B[(kB+4 )*HD + n0+bn];
            pb2 = B[(kB+8 )*HD + n0+bn]; pb3 = B[(kB+12)*HD + n0+bn];
        }
        #pragma unroll
        for (int k=0; k<16; k++){
            ull a0 = As2[k*33+tr], a1 = As2[k*33+tr+16];
            float4 bf = *(const float4*)&Bs[k*68 + tc*4];
            ull b0 = ((const ull*)&bf)[0], b1 = ((const ull*)&bf)[1];
            acc[0][0]=ffma2(a0,b0,acc[0][0]); acc[0][1]=ffma2(a0,b1,acc[0][1]);
            acc[1][0]=ffma2(a1,b0,acc[1][0]); acc[1][1]=ffma2(a1,b1,acc[1][1]);
        }
        __syncthreads();
    }
    float* P = g_part + (size_t)blockIdx.z*MN;
    #pragma unroll
    for (int rr=0; rr<2; rr++){
        int gm = m0 + tr + rr*16;
        if (gm < MD){
            ull* cp = (ull*)(P + gm*HD + n0 + tc*4);
            cp[0] = acc[rr][0]; cp[1] = acc[rr][1];
        }
    }
}

// sum S slices per job (float4)
__global__ void k_red(int S, int njobs, int d0, int d1, int d2, int d3){
    int i4 = blockIdx.x*256 + threadIdx.x;
    if (i4 >= njobs*12800) return;
    int job = i4 / 12800, e4 = i4 - job*12800;
    const float4* P = (const float4*)g_part;
    float4 s = make_float4(0.f,0.f,0.f,0.f);
    for (int z=0; z<S; z++){
        float4 v = P[(size_t)(job*S+z)*12800 + e4];
        s.x+=v.x; s.y+=v.y; s.z+=v.z; s.w+=v.w;
    }
    int dc = (job==0)?d0:(job==1)?d1:(job==2)?d2:d3;
    ((float4*)sel_buf(dc))[e4] = s;
}

// ---------------- edge logits + pair compaction. grid (100,13), 256 thr ----------------
__global__ void k_el(const float* __restrict__ bel, const float* __restrict__ Wee,
                     const float* __restrict__ bee, float* __restrict__ out_lg){
    __shared__ float sWee[4*HD];
    __shared__ float sbel[HD];
    const int t = threadIdx.x;
    #pragma unroll
    for (int q=0; q<8; q++) sWee[t + q*256] = Wee[t + q*256];
    sbel[t] = bel[t]; sbel[t+256] = bel[t+256];
    __syncthreads();
    const int i = blockIdx.x;
    const int w = t >> 5, lane = t & 31;
    const int j = blockIdx.y*8 + w;
    if (j >= MD) return;
    const float* Ar = g_A + i*HD;
    const float* Br = g_B + j*HD;
    float p0=0.f, p1=0.f, p2=0.f, p3=0.f;
    #pragma unroll
    for (int s=0; s<16; s++){
        int h = lane + s*32;
        float v = fmaxf(Ar[h] + Br[h] + sbel[h], 0.f);
        p0 += v*sWee[h]; p1 += v*sWee[HD+h]; p2 += v*sWee[2*HD+h]; p3 += v*sWee[3*HD+h];
    }
    #pragma unroll
    for (int o=16; o; o>>=1){
        p0 += __shfl_xor_sync(~0u, p0, o);
        p1 += __shfl_xor_sync(~0u, p1, o);
        p2 += __shfl_xor_sync(~0u, p2, o);
        p3 += __shfl_xor_sync(~0u, p3, o);
    }
    if (lane == 0){
        p0 += bee[0]; p1 += bee[1]; p2 += bee[2]; p3 += bee[3];
        int p = i*MD + j;
        *(float4*)(out_lg + p*4) = make_float4(p0, p1, p2, p3);
        if (g_nodeok[i] && g_nodeok[j] && (p0>0.f || p1>0.f || p2>0.f || p3>0.f)){
            int pos = atomicAdd(&g_paircnt, 1);
            g_pairlist[pos] = p;
        }
    }
}

// ---------------- gathered edge GEMM via TF32 tensor cores (3xTF32, mask split) ----------------
// grid (8,157), 256 thr = 8 warps. Tile 64 pairs x 64 cols, BOTH iterations.
__global__ void k_ce(const float* __restrict__ We0, const float* __restrict__ We1,
                     const float* __restrict__ bel){
    __shared__ int   pp[64], pi[64], pj[64];
    __shared__ float sbel[HD];
    __shared__ __align__(16) float2 As [16*68];   // [k][row]
    __shared__ __align__(16) float2 Bs0[16*68];   // [k][n]
    __shared__ __align__(16) float2 Bs1[16*68];
    const int cnt = g_paircnt;
    const int m0  = blockIdx.y*64;
    if (m0 >= cnt) return;
    const int n0 = blockIdx.x*64;
    const int t = threadIdx.x;
    if (t < 64){
        int p = (m0 + t < cnt) ? g_pairlist[m0 + t] : g_pairlist[m0];
        pp[t] = p; pi[t] = (p/MD)*HD; pj[t] = (p%MD)*HD;
    }
    sbel[t] = bel[t]; sbel[t+256] = bel[t+256];
    __syncthreads();
    // loader mappings
    const int lr  = t & 63, lk4 = (t >> 6)*4;     // A: row, 4 consecutive k
    const int bk  = t >> 4, bn4 = (t & 15)*4;     // B: k-row, 4 consecutive n
    const int piR = pi[lr], pjR = pj[lr];
    // warp/mma mappings
    const int w = t >> 5, lane = t & 31;
    const int mw = w & 1, nw = w >> 1;
    const int g  = lane >> 2, ctg = lane & 3;
    float4 va, vb, w0, w1;
    va = *(const float4*)&g_A[piR + lk4];
    vb = *(const float4*)&g_B[pjR + lk4];
    w0 = *(const float4*)&We0[bk*HD + n0 + bn4];
    w1 = *(const float4*)&We1[bk*HD + n0 + bn4];
    float4 acc[2][2][2];   // [iter][mt][nt]
    #pragma unroll
    for (int i1=0;i1<2;i1++)
        #pragma unroll
        for (int i2=0;i2<2;i2++)
            #pragma unroll
            for (int i3=0;i3<2;i3++) acc[i1][i2][i3] = make_float4(0.f,0.f,0.f,0.f);
    for (int kt=0; kt<32; kt++){
        {   // mask-split + stage current tile (pure ALU, no cvt)
            const int kb2 = kt*16;
            As[(lk4  )*68 + lr] = tfsplit(fmaxf(va.x + vb.x + sbel[kb2 + lk4    ], 0.f));
            As[(lk4+1)*68 + lr] = tfsplit(fmaxf(va.y + vb.y + sbel[kb2 + lk4 + 1], 0.f));
            As[(lk4+2)*68 + lr] = tfsplit(fmaxf(va.z + vb.z + sbel[kb2 + lk4 + 2], 0.f));
            As[(lk4+3)*68 + lr] = tfsplit(fmaxf(va.w + vb.w + sbel[kb2 + lk4 + 3], 0.f));
            float2 s0 = tfsplit(w0.x), s1 = tfsplit(w0.y), s2 = tfsplit(w0.z), s3 = tfsplit(w0.w);
            float4* bp0 = (float4*)&Bs0[bk*68 + bn4];
            bp0[0] = make_float4(s0.x, s0.y, s1.x, s1.y);
            bp0[1] = make_float4(s2.x, s2.y, s3.x, s3.y);
            float2 u0 = tfsplit(w1.x), u1 = tfsplit(w1.y), u2 = tfsplit(w1.z), u3 = tfsplit(w1.w);
            float4* bp1 = (float4*)&Bs1[bk*68 + bn4];
            bp1[0] = make_float4(u0.x, u0.y, u1.x, u1.y);
            bp1[1] = make_float4(u2.x, u2.y, u3.x, u3.y);
        }
        __syncthreads();
        if (kt+1 < 32){
            int ko = (kt+1)*16;
            va = *(const float4*)&g_A[piR + ko + lk4];
            vb = *(const float4*)&g_B[pjR + ko + lk4];
            w0 = *(const float4*)&We0[(ko + bk)*HD + n0 + bn4];
            w1 = *(const float4*)&We1[(ko + bk)*HD + n0 + bn4];
        }
        #pragma unroll
        for (int ks=0; ks<16; ks+=8){
            float2 af[2][4];
            #pragma unroll
            for (int mt=0; mt<2; mt++){
                int mo = mw*32 + mt*16;
                af[mt][0] = As[(ks+ctg  )*68 + mo + g];
                af[mt][1] = As[(ks+ctg  )*68 + mo + g + 8];
                af[mt][2] = As[(ks+ctg+4)*68 + mo + g];
                af[mt][3] = As[(ks+ctg+4)*68 + mo + g + 8];
            }
            #pragma unroll
            for (int it=0; it<2; it++){
                const float2* Bsm = it ? Bs1 : Bs0;
                #pragma unroll
                for (int nt=0; nt<2; nt++){
                    int no = nw*16 + nt*8;
                    float2 bf0 = Bsm[(ks+ctg  )*68 + no + g];
                    float2 bf1 = Bsm[(ks+ctg+4)*68 + no + g];
                    unsigned bh0 = __float_as_uint(bf0.x), bh1 = __float_as_uint(bf1.x);
                    unsigned bl0 = __float_as_uint(bf0.y), bl1 = __float_as_uint(bf1.y);
                    #pragma unroll
                    for (int mt=0; mt<2; mt++){
                        unsigned ah0 = __float_as_uint(af[mt][0].x);
                        unsigned ah1 = __float_as_uint(af[mt][1].x);
                        unsigned ah2 = __float_as_uint(af[mt][2].x);
                        unsigned ah3 = __float_as_uint(af[mt][3].x);
                        unsigned al0 = __float_as_uint(af[mt][0].y);
                        unsigned al1 = __float_as_uint(af[mt][1].y);
                        unsigned al2 = __float_as_uint(af[mt][2].y);
                        unsigned al3 = __float_as_uint(af[mt][3].y);
                        float4& d = acc[it][mt][nt];
                        mma_tf32(d, ah0, ah1, ah2, ah3, bh0, bh1);   // hi*hi
                        mma_tf32(d, ah0, ah1, ah2, ah3, bl0, bl1);   // hi*lo
                        mma_tf32(d, al0, al1, al2, al3, bh0, bh1);   // lo*hi
                    }
                }
            }
        }
        __syncthreads();
    }
    #pragma unroll
    for (int it=0; it<2; it++){
        float* C = it ? g_Ce1 : g_Ce0;
        #pragma unroll
        for (int mt=0; mt<2; mt++){
            #pragma unroll
            for (int nt=0; nt<2; nt++){
                float4 d = acc[it][mt][nt];
                int rl0 = mw*32 + mt*16 + g;
                int col = n0 + nw*16 + nt*8 + ctg*2;
                if (m0 + rl0 < cnt){
                    float* p = C + pp[rl0]*HD + col;
                    p[0] = d.x; p[1] = d.y;
                }
                int rl1 = rl0 + 8;
                if (m0 + rl1 < cnt){
                    float* p = C + pp[rl1]*HD + col;
                    p[0] = d.z; p[1] = d.w;
                }
            }
        }
    }
}

// ---------------- message pass + scatter-sum. grid 100, 512 thr, 4-deep prefetch ----------------
__global__ void k_msg(int it, const float* __restrict__ lgg,
                      const float* __restrict__ Wt, const float* __restrict__ bne){
    __shared__ float lg[400];
    __shared__ int   jl[100];
    __shared__ int   njl;
    const float* childin  = it ? g_child1 : g_child0;
    float*       childout = it ? g_child2 : g_child1;
    const float* Ce       = it ? g_Ce1    : g_Ce0;
    const int i = blockIdx.x, h = threadIdx.x;
    if (h < 400) lg[h] = lgg[i*400 + h];
    __syncthreads();
    if (h == 0){
        int n = 0;
        if (g_nodeok[i]){
            for (int j=0; j<MD; j++){
                if (!g_nodeok[j]) continue;
                if (lg[j*4]>0.f || lg[j*4+1]>0.f || lg[j*4+2]>0.f || lg[j*4+3]>0.f) jl[n++] = j;
            }
        }
        njl = n;
    }
    __syncthreads();
    float cin = childin[i*HD + h];
    bool any = (g_paircnt > 0);
    float acc = 0.f;
    const int n = njl;
    float base_i = g_Ai[i*HD + h] + bne[h];
    float wt0 = Wt[h], wt1 = Wt[HD+h], wt2 = Wt[2*HD+h], wt3 = Wt[3*HD+h];
    const float* CeI = Ce + (long long)i*MD*HD;

    #define MSG_BODY(JB, CB, CC) { \
        float l0 = lg[(JB)*4], l1 = lg[(JB)*4+1], l2 = lg[(JB)*4+2], l3 = lg[(JB)*4+3]; \
        float base = base_i + (CB) + (CC); \
        if (l0 > 0.f) acc += fmaxf(fmaf(l0, wt0, base), 0.f); \
        if (l1 > 0.f) acc += fmaxf(fmaf(l1, wt1, base), 0.f); \
        if (l2 > 0.f) acc += fmaxf(fmaf(l2, wt2, base), 0.f); \
        if (l3 > 0.f) acc += fmaxf(fmaf(l3, wt3, base), 0.f); }

    float b0=0,b1=0,b2=0,b3=0,c0=0,c1=0,c2=0,c3=0;
    if (n > 0){ int j=jl[0]; b0=g_Bj[j*HD+h]; c0=CeI[j*HD+h]; }
    if (n > 1){ int j=jl[1]; b1=g_Bj[j*HD+h]; c1=CeI[j*HD+h]; }
    if (n > 2){ int j=jl[2]; b2=g_Bj[j*HD+h]; c2=CeI[j*HD+h]; }
    if (n > 3){ int j=jl[3]; b3=g_Bj[j*HD+h]; c3=CeI[j*HD+h]; }
    int q = 0;
    const int nq = n & ~3;
    for (; q < nq; q += 4){
        float tb0=b0, tc0=c0, tb1=b1, tc1=c1, tb2=b2, tc2=c2, tb3=b3, tc3=c3;
        if (q+4 < n){ int j=jl[q+4]; b0=g_Bj[j*HD+h]; c0=CeI[j*HD+h]; }
        if (q+5 < n){ int j=jl[q+5]; b1=g_Bj[j*HD+h]; c1=CeI[j*HD+h]; }
        if (q+6 < n){ int j=jl[q+6]; b2=g_Bj[j*HD+h]; c2=CeI[j*HD+h]; }
        if (q+7 < n){ int j=jl[q+7]; b3=g_Bj[j*HD+h]; c3=CeI[j*HD+h]; }
        MSG_BODY(jl[q  ], tb0, tc0);
        MSG_BODY(jl[q+1], tb1, tc1);
        MSG_BODY(jl[q+2], tb2, tc2);
        MSG_BODY(jl[q+3], tb3, tc3);
    }
    for (; q < n; q++){
        int j = jl[q];
        float cb = g_Bj[j*HD+h], cc = CeI[j*HD+h];
        MSG_BODY(j, cb, cc);
    }
    #undef MSG_BODY
    childout[i*HD + h] = any ? acc : cin;
}

// ---------------- heads partials with inline h-reduce. grid (9,4,4) ----------------
__device__ __forceinline__ float hval(int gm, int k, const float* __restrict__ bc){
    float s = 0.f;
    #pragma unroll
    for (int z=0; z<8; z++) s += g_part[(size_t)z*MN + gm*HD + k];
    return fmaxf(s + bc[k], 0.f);
}
__global__ void k_heads(const float* __restrict__ Wc2, const float* __restrict__ Ws,
                        const float* __restrict__ bc){
    __shared__ ull   As2[16*33];
    __shared__ float Bs[16*68];
    const bool semjob = (blockIdx.x == 8);
    const float* B = semjob ? Ws : Wc2;
    const int N   = semjob ? 57 : 512;
    const int n0  = semjob ? 0  : blockIdx.x*64;
    const int m0  = blockIdx.y*32;
    const int kb  = blockIdx.z*128;
    const int t = threadIdx.x, tr = t>>4, tc = t&15;
    const int ar0 = t>>4, ak = t&15, ar1 = ar0+16;
    const int bn = t&63, bk0 = t>>6;
    const int gm0 = m0+ar0, gm1 = m0+ar1;
    const bool bok = (n0 + bn) < N;
    float pa0, pa1, pb0, pb1, pb2, pb3;
    {
        int k = kb + ak;
        pa0 = (gm0 < MD) ? hval(gm0, k, bc) : 0.f;
        pa1 = (gm1 < MD) ? hval(gm1, k, bc) : 0.f;
        int kB = kb + bk0;
        pb0 = bok ? B[(kB   )*N + n0+bn] : 0.f;
        pb1 = bok ? B[(kB+4 )*N + n0+bn] : 0.f;
        pb2 = bok ? B[(kB+8 )*N + n0+bn] : 0.f;
        pb3 = bok ? B[(kB+12)*N + n0+bn] : 0.f;
    }
    ull acc[2][2] = {};
    for (int kt=0; kt<8; kt++){
        As2[ak*33 + ar0] = dup2(pa0);
        As2[ak*33 + ar1] = dup2(pa1);
        Bs[(bk0   )*68 + bn] = pb0;
        Bs[(bk0+4 )*68 + bn] = pb1;
        Bs[(bk0+8 )*68 + bn] = pb2;
        Bs[(bk0+12)*68 + bn] = pb3;
        __syncthreads();
        if (kt+1 < 8){
            int k = kb + (kt+1)*16 + ak;
            pa0 = (gm0 < MD) ? hval(gm0, k, bc) : 0.f;
            pa1 = (gm1 < MD) ? hval(gm1, k, bc) : 0.f;
            int kB = kb + (kt+1)*16 + bk0;
            pb0 = bok ? B[(kB   )*N + n0+bn] : 0.f;
            pb1 = bok ? B[(kB+4 )*N + n0+bn] : 0.f;
            pb2 = bok ? B[(kB+8 )*N + n0+bn] : 0.f;
            pb3 = bok ? B[(kB+12)*N + n0+bn] : 0.f;
        }
        #pragma unroll
        for (int k=0; k<16; k++){
            ull a0 = As2[k*33+tr], a1 = As2[k*33+tr+16];
            float4 bf = *(const float4*)&Bs[k*68 + tc*4];
            ull b0 = ((const ull*)&bf)[0], b1 = ((const ull*)&bf)[1];
            acc[0][0]=ffma2(a0,b0,acc[0][0]); acc[0][1]=ffma2(a0,b1,acc[0][1]);
            acc[1][0]=ffma2(a1,b0,acc[1][0]); acc[1][1]=ffma2(a1,b1,acc[1][1]);
        }
        __syncthreads();
    }
    const int sl = blockIdx.z;
    #pragma unroll
    for (int rr=0; rr<2; rr++){
        int gm = m0 + tr + rr*16;
        if (gm >= MD) continue;
        float r0 = __uint_as_float((unsigned)(acc[rr][0]      ));
        float r1 = __uint_as_float((unsigned)(acc[rr][0] >> 32));
        float r2 = __uint_as_float((unsigned)(acc[rr][1]      ));
        float r3 = __uint_as_float((unsigned)(acc[rr][1] >> 32));
        int gn = n0 + tc*4;
        if (!semjob){
            ull* cp = (ull*)(g_part + (size_t)(8+sl)*MN + gm*HD + gn);
            cp[0] = acc[rr][0]; cp[1] = acc[rr][1];
        } else {
            float* P = g_partS + sl*5700 + gm*57;
            if (gn   < 57) P[gn  ] = r0;
            if (gn+1 < 57) P[gn+1] = r1;
            if (gn+2 < 57) P[gn+2] = r2;
            if (gn+3 < 57) P[gn+3] = r3;
        }
    }
}

// final output reduce. blocks 0..49: child_out float4 (part slices 8..11), 50..72: sem scalar.
__global__ void k_out(const float* __restrict__ bc2, const float* __restrict__ bs,
                      float* __restrict__ out_co, float* __restrict__ out_sem){
    if (blockIdx.x < 50){
        int i4 = blockIdx.x*256 + threadIdx.x;
        const float4* P = (const float4*)g_part;
        float4 s = make_float4(0.f,0.f,0.f,0.f);
        #pragma unroll
        for (int z=0; z<4; z++){
            float4 v = P[(size_t)(8+z)*12800 + i4];
            s.x+=v.x; s.y+=v.y; s.z+=v.z; s.w+=v.w;
        }
        float4 b = ((const float4*)bc2)[i4 & 127];
        s.x = fmaxf(s.x+b.x,0.f); s.y = fmaxf(s.y+b.y,0.f);
        s.z = fmaxf(s.z+b.z,0.f); s.w = fmaxf(s.w+b.w,0.f);
        ((float4*)out_co)[i4] = s;
    } else {
        int e = (blockIdx.x-50)*256 + threadIdx.x;
        if (e >= 5700) return;
        float s = 0.f;
        #pragma unroll
        for (int z=0; z<4; z++) s += g_partS[z*5700 + e];
        out_sem[e] = s + bs[e % 57];
    }
}

// ---------------- launch: 13 kernels ----------------
extern "C" void kernel_launch(void* const* d_in, const int* in_sizes, int n_in,
                              void* d_out, int out_size){
    const float* pf  = (const float*)d_in[0];
    const float* Wp  = (const float*)d_in[1];
    const float* bp  = (const float*)d_in[2];
    const float* Wx  = (const float*)d_in[3];
    const float* bx  = (const float*)d_in[4];
    const float* Wel = (const float*)d_in[5];
    const float* bel = (const float*)d_in[6];
    const float* Wee = (const float*)d_in[7];
    const float* bee = (const float*)d_in[8];
    const float* Wne = (const float*)d_in[9];
    const float* bne = (const float*)d_in[10];
    const float* Wc  = (const float*)d_in[11];
    const float* bc  = (const float*)d_in[12];
    const float* Ws  = (const float*)d_in[13];
    const float* bs  = (const float*)d_in[14];
    const float* Wc2 = (const float*)d_in[15];
    const float* bc2 = (const float*)d_in[16];

    float* out     = (float*)d_out;
    float* out_co  = out;
    float* out_sem = out + 51200;
    float* out_ex  = out + 56900;
    float* out_lg  = out + 57000;

    k_gemv_part<<<dim3(50,4),256>>>(pf, Wp);
    k_gemv_fin<<<100,128>>>(bp, Wx, bx, out_ex);
    k_gp<<<dim3(8,4,16),256>>>(5 | (5<<8) | (5<<16) | (5<<24), 512, 4,
                               Wel, Wel + 512*512, Wne, Wne + 512*512);
    k_red<<<200,256>>>(4, 4, 0, 1, 2, 3);
    k_el<<<dim3(100,13),256>>>(bel, Wee, bee, out_lg);
    k_ce<<<dim3(8,157),256>>>(Wne + 1024*512, Wne + (1540+1024)*512, bel);
    k_msg<<<100,512>>>(0, out_lg, Wne + 1536*512, bne);
    k_gp<<<dim3(8,4,8),256>>>(6 | (6<<8), 512, 4,
                              Wne + 1540*512, Wne + (1540+512)*512, Wne, Wne);
    k_red<<<100,256>>>(4, 2, 2, 3, 0, 0);
    k_msg<<<100,512>>>(1, out_lg, Wne + (1540+1536)*512, bne + 512);
    k_gp<<<dim3(8,4,8),256>>>(9, 1536, 8, Wc, Wc, Wc, Wc);
    k_heads<<<dim3(9,4,4),256>>>(Wc2, Ws, bc);
    k_out<<<73,256>>>(bc2, bs, out_co, out_sem);
}

// round 17
// speedup vs baseline: 1.2309x; 1.0059x over previous
#include <cuda_runtime.h>

typedef unsigned long long ull;

#define MD 100
#define HD 512
#define NP 10000
#define MN 51200

// ---------------- device scratch ----------------
__device__ __align__(16) float g_child0[MD*HD];
__device__ __align__(16) float g_child1[MD*HD];
__device__ __align__(16) float g_child2[MD*HD];
__device__ __align__(16) float g_A[MD*HD];
__device__ __align__(16) float g_B[MD*HD];
__device__ __align__(16) float g_Ai[MD*HD];
__device__ __align__(16) float g_Bj[MD*HD];
__device__ __align__(16) float g_Ce0[NP*HD];
__device__ __align__(16) float g_Ce1[NP*HD];
__device__ __align__(16) float g_gpart[4*MN];
__device__ __align__(16) float g_part[16*MN];
__device__ __align__(16) float g_partS[4*5700];
__device__ int   g_nodeok[MD];
__device__ int   g_pairlist[NP];
__device__ int   g_paircnt;

__device__ __forceinline__ ull ffma2(ull a, ull b, ull c){
    ull d;
    asm("fma.rn.f32x2 %0, %1, %2, %3;" : "=l"(d) : "l"(a), "l"(b), "l"(c));
    return d;
}
__device__ __forceinline__ ull dup2(float v){
    unsigned u = __float_as_uint(v);
    return ((ull)u << 32) | (ull)u;
}
// truncating tf32 split via mask (full-rate ALU; validated rel_err ~1.36e-6)
__device__ __forceinline__ float2 tfsplit(float v){
    float hi = __uint_as_float(__float_as_uint(v) & 0xFFFFE000u);
    float lo = v - hi;
    lo = __uint_as_float(__float_as_uint(lo) & 0xFFFFE000u);
    return make_float2(hi, lo);
}
__device__ __forceinline__ void mma_tf32(float4& d, unsigned a0, unsigned a1,
                                         unsigned a2, unsigned a3,
                                         unsigned b0, unsigned b1){
    asm volatile("mma.sync.aligned.m16n8k8.row.col.f32.tf32.tf32.f32 "
                 "{%0,%1,%2,%3}, {%4,%5,%6,%7}, {%8,%9}, {%0,%1,%2,%3};"
                 : "+f"(d.x), "+f"(d.y), "+f"(d.z), "+f"(d.w)
                 : "r"(a0), "r"(a1), "r"(a2), "r"(a3), "r"(b0), "r"(b1));
}
__device__ __forceinline__ float* sel_buf(int code){
    switch (code){
        case 0: return g_A;      case 1: return g_B;
        case 2: return g_Ai;     case 3: return g_Bj;
        case 4: return g_part;   case 5: return g_child0;
        case 6: return g_child1; default: return g_child2;
    }
}
__device__ __forceinline__ float fetchA(int code, int m, int k){
    if (code == 9){   // virtual concat [child0|child1|child2]
        int q = k >> 9, kk = k & 511;
        const float* s = (q==0) ? g_child0 : (q==1) ? g_child1 : g_child2;
        return s[m*HD + kk];
    }
    return sel_buf(code)[m*HD + k];
}

// ---------------- parent GEMV: float4, split-K. grid (50,4), 256 thr ----------------
__global__ void k_gemv_part(const float* __restrict__ pf, const float* __restrict__ Wp){
    __shared__ float pfs[128];
    const int z = blockIdx.y;
    const int c4 = blockIdx.x*256 + threadIdx.x;
    if (threadIdx.x < 128) pfs[threadIdx.x] = pf[z*128 + threadIdx.x];
    __syncthreads();
    const float4* w = (const float4*)Wp + (long long)(z*128)*12800 + c4;
    float4 a = make_float4(0.f,0.f,0.f,0.f);
    #pragma unroll 8
    for (int k=0; k<128; k++){
        float4 wv = w[(long long)k*12800];
        float s = pfs[k];
        a.x += s*wv.x; a.y += s*wv.y; a.z += s*wv.z; a.w += s*wv.w;
    }
    ((float4*)g_gpart)[z*12800 + c4] = a;
}

// finisher + exists logits fused. grid 100, 128 thr.
__global__ void k_gemv_fin(const float* __restrict__ bp, const float* __restrict__ Wx,
                           const float* __restrict__ bx, float* __restrict__ out_ex){
    __shared__ float red[4];
    const int m = blockIdx.x, t = threadIdx.x;
    const int c4 = m*128 + t;
    const float4* gp = (const float4*)g_gpart;
    float4 s0 = gp[c4], s1 = gp[12800+c4], s2 = gp[2*12800+c4], s3 = gp[3*12800+c4];
    float4 b  = ((const float4*)bp)[c4];
    float4 v;
    v.x = fmaxf(s0.x+s1.x+s2.x+s3.x+b.x, 0.f);
    v.y = fmaxf(s0.y+s1.y+s2.y+s3.y+b.y, 0.f);
    v.z = fmaxf(s0.z+s1.z+s2.z+s3.z+b.z, 0.f);
    v.w = fmaxf(s0.w+s1.w+s2.w+s3.w+b.w, 0.f);
    ((float4*)g_child0)[c4] = v;
    float4 wx = ((const float4*)Wx)[t];
    float p = v.x*wx.x + v.y*wx.y + v.z*wx.z + v.w*wx.w;
    #pragma unroll
    for (int o=16; o; o>>=1) p += __shfl_xor_sync(~0u, p, o);
    if ((t & 31) == 0) red[t>>5] = p;
    __syncthreads();
    if (t == 0){
        float vv = red[0]+red[1]+red[2]+red[3] + bx[0];
        out_ex[m]   = vv;
        g_nodeok[m] = (vv > 0.f) ? 1 : 0;
        if (m == 0) g_paircnt = 0;
    }
}

// ---------------- fused multi-B GEMM: NJ jobs share one A. grid (8,4,4), 256 thr ----------------
// Partials: job j, slice sl -> g_part[(j*4+sl)*MN]. KSL=128.
template<int NJ>
__global__ void k_gpf(int Acode,
                      const float* __restrict__ B0, const float* __restrict__ B1,
                      const float* __restrict__ B2, const float* __restrict__ B3){
    __shared__ ull   As2[16*33];
    __shared__ float Bs[NJ][16*68];
    const float* Bp[4] = {B0, B1, B2, B3};
    const int sl = blockIdx.z;
    const int kb = sl*128;
    const int n0 = blockIdx.x*64, m0 = blockIdx.y*32;
    const int t = threadIdx.x, tr = t>>4, tc = t&15;
    const int ar0 = t>>4, ak = t&15, ar1 = ar0+16;
    const int bn = t&63, bk0 = t>>6;
    const int gm0 = m0+ar0, gm1 = m0+ar1;
    float pa0, pa1, pb[NJ][4];
    {
        int k = kb + ak;
        pa0 = (gm0 < MD) ? fetchA(Acode, gm0, k) : 0.f;
        pa1 = (gm1 < MD) ? fetchA(Acode, gm1, k) : 0.f;
        int kB = kb + bk0;
        #pragma unroll
        for (int j=0; j<NJ; j++){
            pb[j][0] = Bp[j][(kB   )*HD + n0+bn];
            pb[j][1] = Bp[j][(kB+4 )*HD + n0+bn];
            pb[j][2] = Bp[j][(kB+8 )*HD + n0+bn];
            pb[j][3] = Bp[j][(kB+12)*HD + n0+bn];
        }
    }
    ull acc[NJ][2][2] = {};
    for (int kt=0; kt<8; kt++){
        As2[ak*33 + ar0] = dup2(pa0);
        As2[ak*33 + ar1] = dup2(pa1);
        #pragma unroll
        for (int j=0; j<NJ; j++){
            Bs[j][(bk0   )*68 + bn] = pb[j][0];
            Bs[j][(bk0+4 )*68 + bn] = pb[j][1];
            Bs[j][(bk0+8 )*68 + bn] = pb[j][2];
            Bs[j][(bk0+12)*68 + bn] = pb[j][3];
        }
        __syncthreads();
        if (kt+1 < 8){
            int k = kb + (kt+1)*16 + ak;
            pa0 = (gm0 < MD) ? fetchA(Acode, gm0, k) : 0.f;
            pa1 = (gm1 < MD) ? fetchA(Acode, gm1, k) : 0.f;
            int kB = kb + (kt+1)*16 + bk0;
            #pragma unroll
            for (int j=0; j<NJ; j++){
                pb[j][0] = Bp[j][(kB   )*HD + n0+bn];
                pb[j][1] = Bp[j][(kB+4 )*HD + n0+bn];
                pb[j][2] = Bp[j][(kB+8 )*HD + n0+bn];
                pb[j][3] = Bp[j][(kB+12)*HD + n0+bn];
            }
        }
        #pragma unroll
        for (int k=0; k<16; k++){
            ull a0 = As2[k*33+tr], a1 = As2[k*33+tr+16];
            #pragma unroll
            for (int j=0; j<NJ; j++){
                float4 bf = *(const float4*)&Bs[j][k*68 + tc*4];
                ull b0 = ((const ull*)&bf)[0], b1 = ((const ull*)&bf)[1];
                acc[j][0][0]=ffma2(a0,b0,acc[j][0][0]); acc[j][0][1]=ffma2(a0,b1,acc[j][0][1]);
                acc[j][1][0]=ffma2(a1,b0,acc[j][1][0]); acc[j][1][1]=ffma2(a1,b1,acc[j][1][1]);
            }
        }
        __syncthreads();
    }
    #pragma unroll
    for (int j=0; j<NJ; j++){
        float* P = g_part + (size_t)(j*4 + sl)*MN;
        #pragma unroll
        for (int rr=0; rr<2; rr++){
            int gm = m0 + tr + rr*16;
            if (gm < MD){
                ull* cp = (ull*)(P + gm*HD + n0 + tc*4);
                cp[0] = acc[j][rr][0]; cp[1] = acc[j][rr][1];
            }
        }
    }
}

// ---------------- single-job split-K GEMM (h path, K=1536). grid (8,4,8) ----------------
__global__ void k_gp(int Acode, int Klen, int KS,
                     const float* __restrict__ B){
    __shared__ ull   As2[16*33];
    __shared__ float Bs[16*68];
    const int KSL = Klen / KS;
    const int sl = blockIdx.z;
    const int kb = sl*KSL;
    const int n0 = blockIdx.x*64, m0 = blockIdx.y*32;
    const int t = threadIdx.x, tr = t>>4, tc = t&15;
    const int ar0 = t>>4, ak = t&15, ar1 = ar0+16;
    const int bn = t&63, bk0 = t>>6;
    const int gm0 = m0+ar0, gm1 = m0+ar1;
    float pa0, pa1, pb0, pb1, pb2, pb3;
    {
        int k = kb + ak;
        pa0 = (gm0 < MD) ? fetchA(Acode, gm0, k) : 0.f;
        pa1 = (gm1 < MD) ? fetchA(Acode, gm1, k) : 0.f;
        int kB = kb + bk0;
        pb0 = B[(kB   )*HD + n0+bn]; pb1 = B[(kB+4 )*HD + n0+bn];
        pb2 = B[(kB+8 )*HD + n0+bn]; pb3 = B[(kB+12)*HD + n0+bn];
    }
    ull acc[2][2] = {};
    const int nkt = KSL/16;
    for (int kt=0; kt<nkt; kt++){
        As2[ak*33 + ar0] = dup2(pa0);
        As2[ak*33 + ar1] = dup2(pa1);
        Bs[(bk0   )*68 + bn] = pb0;
        Bs[(bk0+4 )*68 + bn] = pb1;
        Bs[(bk0+8 )*68 + bn] = pb2;
        Bs[(bk0+12)*68 + bn] = pb3;
        __syncthreads();
        if (kt+1 < nkt){
            int k = kb + (kt+1)*16 + ak;
            pa0 = (gm0 < MD) ? fetchA(Acode, gm0, k) : 0.f;
            pa1 = (gm1 < MD) ? fetchA(Acode, gm1, k) : 0.f;
            int kB = kb + (kt+1)*16 + bk0;
            pb0 = B[(kB   )*HD + n0+bn]; pb1 = B[(kB+4 )*HD + n0+bn];
            pb2 = B[(kB+8 )*HD + n0+bn]; pb3 = B[(kB+12)*HD + n0+bn];
        }
        #pragma unroll
        for (int k=0; k<16; k++){
            ull a0 = As2[k*33+tr], a1 = As2[k*33+tr+16];
            float4 bf = *(const float4*)&Bs[k*68 + tc*4];
            ull b0 = ((const ull*)&bf)[0], b1 = ((const ull*)&bf)[1];
            acc[0][0]=ffma2(a0,b0,acc[0][0]); acc[0][1]=ffma2(a0,b1,acc[0][1]);
            acc[1][0]=ffma2(a1,b0,acc[1][0]); acc[1][1]=ffma2(a1,b1,acc[1][1]);
        }
        __syncthreads();
    }
    float* P = g_part + (size_t)blockIdx.z*MN;
    #pragma unroll
    for (int rr=0; rr<2; rr++){
        int gm = m0 + tr + rr*16;
        if (gm < MD){
            ull* cp = (ull*)(P + gm*HD + n0 + tc*4);
            cp[0] = acc[rr][0]; cp[1] = acc[rr][1];
        }
    }
}

// sum S slices per job (float4)
__global__ void k_red(int S, int njobs, int d0, int d1, int d2, int d3){
    int i4 = blockIdx.x*256 + threadIdx.x;
    if (i4 >= njobs*12800) return;
    int job = i4 / 12800, e4 = i4 - job*12800;
    const float4* P = (const float4*)g_part;
    float4 s = make_float4(0.f,0.f,0.f,0.f);
    for (int z=0; z<S; z++){
        float4 v = P[(size_t)(job*S+z)*12800 + e4];
        s.x+=v.x; s.y+=v.y; s.z+=v.z; s.w+=v.w;
    }
    int dc = (job==0)?d0:(job==1)?d1:(job==2)?d2:d3;
    ((float4*)sel_buf(dc))[e4] = s;
}

// ---------------- edge logits + pair compaction. grid (100,13), 256 thr ----------------
__global__ void k_el(const float* __restrict__ bel, const float* __restrict__ Wee,
                     const float* __restrict__ bee, float* __restrict__ out_lg){
    __shared__ float sWee[4*HD];
    __shared__ float sbel[HD];
    const int t = threadIdx.x;
    #pragma unroll
    for (int q=0; q<8; q++) sWee[t + q*256] = Wee[t + q*256];
    sbel[t] = bel[t]; sbel[t+256] = bel[t+256];
    __syncthreads();
    const int i = blockIdx.x;
    const int w = t >> 5, lane = t & 31;
    const int j = blockIdx.y*8 + w;
    if (j >= MD) return;
    const float* Ar = g_A + i*HD;
    const float* Br = g_B + j*HD;
    float p0=0.f, p1=0.f, p2=0.f, p3=0.f;
    #pragma unroll
    for (int s=0; s<16; s++){
        int h = lane + s*32;
        float v = fmaxf(Ar[h] + Br[h] + sbel[h], 0.f);
        p0 += v*sWee[h]; p1 += v*sWee[HD+h]; p2 += v*sWee[2*HD+h]; p3 += v*sWee[3*HD+h];
    }
    #pragma unroll
    for (int o=16; o; o>>=1){
        p0 += __shfl_xor_sync(~0u, p0, o);
        p1 += __shfl_xor_sync(~0u, p1, o);
        p2 += __shfl_xor_sync(~0u, p2, o);
        p3 += __shfl_xor_sync(~0u, p3, o);
    }
    if (lane == 0){
        p0 += bee[0]; p1 += bee[1]; p2 += bee[2]; p3 += bee[3];
        int p = i*MD + j;
        *(float4*)(out_lg + p*4) = make_float4(p0, p1, p2, p3);
        if (g_nodeok[i] && g_nodeok[j] && (p0>0.f || p1>0.f || p2>0.f || p3>0.f)){
            int pos = atomicAdd(&g_paircnt, 1);
            g_pairlist[pos] = p;
        }
    }
}

// ---------------- gathered edge GEMM via TF32 tensor cores (3xTF32, mask split) ----------------
// grid (8,157), 256 thr = 8 warps. Tile 64 pairs x 64 cols, BOTH iterations.
__global__ void k_ce(const float* __restrict__ We0, const float* __restrict__ We1,
                     const float* __restrict__ bel){
    __shared__ int   pp[64], pi[64], pj[64];
    __shared__ float sbel[HD];
    __shared__ __align__(16) float2 As [16*68];   // [k][row]
    __shared__ __align__(16) float2 Bs0[16*68];   // [k][n]
    __shared__ __align__(16) float2 Bs1[16*68];
    const int cnt = g_paircnt;
    const int m0  = blockIdx.y*64;
    if (m0 >= cnt) return;
    const int n0 = blockIdx.x*64;
    const int t = threadIdx.x;
    if (t < 64){
        int p = (m0 + t < cnt) ? g_pairlist[m0 + t] : g_pairlist[m0];
        pp[t] = p; pi[t] = (p/MD)*HD; pj[t] = (p%MD)*HD;
    }
    sbel[t] = bel[t]; sbel[t+256] = bel[t+256];
    __syncthreads();
    const int lr  = t & 63, lk4 = (t >> 6)*4;
    const int bk  = t >> 4, bn4 = (t & 15)*4;
    const int piR = pi[lr], pjR = pj[lr];
    const int w = t >> 5, lane = t & 31;
    const int mw = w & 1, nw = w >> 1;
    const int g  = lane >> 2, ctg = lane & 3;
    float4 va, vb, w0, w1;
    va = *(const float4*)&g_A[piR + lk4];
    vb = *(const float4*)&g_B[pjR + lk4];
    w0 = *(const float4*)&We0[bk*HD + n0 + bn4];
    w1 = *(const float4*)&We1[bk*HD + n0 + bn4];
    float4 acc[2][2][2];
    #pragma unroll
    for (int i1=0;i1<2;i1++)
        #pragma unroll
        for (int i2=0;i2<2;i2++)
            #pragma unroll
            for (int i3=0;i3<2;i3++) acc[i1][i2][i3] = make_float4(0.f,0.f,0.f,0.f);
    for (int kt=0; kt<32; kt++){
        {
            const int kb2 = kt*16;
            As[(lk4  )*68 + lr] = tfsplit(fmaxf(va.x + vb.x + sbel[kb2 + lk4    ], 0.f));
            As[(lk4+1)*68 + lr] = tfsplit(fmaxf(va.y + vb.y + sbel[kb2 + lk4 + 1], 0.f));
            As[(lk4+2)*68 + lr] = tfsplit(fmaxf(va.z + vb.z + sbel[kb2 + lk4 + 2], 0.f));
            As[(lk4+3)*68 + lr] = tfsplit(fmaxf(va.w + vb.w + sbel[kb2 + lk4 + 3], 0.f));
            float2 s0 = tfsplit(w0.x), s1 = tfsplit(w0.y), s2 = tfsplit(w0.z), s3 = tfsplit(w0.w);
            float4* bp0 = (float4*)&Bs0[bk*68 + bn4];
            bp0[0] = make_float4(s0.x, s0.y, s1.x, s1.y);
            bp0[1] = make_float4(s2.x, s2.y, s3.x, s3.y);
            float2 u0 = tfsplit(w1.x), u1 = tfsplit(w1.y), u2 = tfsplit(w1.z), u3 = tfsplit(w1.w);
            float4* bp1 = (float4*)&Bs1[bk*68 + bn4];
            bp1[0] = make_float4(u0.x, u0.y, u1.x, u1.y);
            bp1[1] = make_float4(u2.x, u2.y, u3.x, u3.y);
        }
        __syncthreads();
        if (kt+1 < 32){
            int ko = (kt+1)*16;
            va = *(const float4*)&g_A[piR + ko + lk4];
            vb = *(const float4*)&g_B[pjR + ko + lk4];
            w0 = *(const float4*)&We0[(ko + bk)*HD + n0 + bn4];
            w1 = *(const float4*)&We1[(ko + bk)*HD + n0 + bn4];
        }
        #pragma unroll
        for (int ks=0; ks<16; ks+=8){
            float2 af[2][4];
            #pragma unroll
            for (int mt=0; mt<2; mt++){
                int mo = mw*32 + mt*16;
                af[mt][0] = As[(ks+ctg  )*68 + mo + g];
                af[mt][1] = As[(ks+ctg  )*68 + mo + g + 8];
                af[mt][2] = As[(ks+ctg+4)*68 + mo + g];
                af[mt][3] = As[(ks+ctg+4)*68 + mo + g + 8];
            }
            #pragma unroll
            for (int it=0; it<2; it++){
                const float2* Bsm = it ? Bs1 : Bs0;
                #pragma unroll
                for (int nt=0; nt<2; nt++){
                    int no = nw*16 + nt*8;
                    float2 bf0 = Bsm[(ks+ctg  )*68 + no + g];
                    float2 bf1 = Bsm[(ks+ctg+4)*68 + no + g];
                    unsigned bh0 = __float_as_uint(bf0.x), bh1 = __float_as_uint(bf1.x);
                    unsigned bl0 = __float_as_uint(bf0.y), bl1 = __float_as_uint(bf1.y);
                    #pragma unroll
                    for (int mt=0; mt<2; mt++){
                        unsigned ah0 = __float_as_uint(af[mt][0].x);
                        unsigned ah1 = __float_as_uint(af[mt][1].x);
                        unsigned ah2 = __float_as_uint(af[mt][2].x);
                        unsigned ah3 = __float_as_uint(af[mt][3].x);
                        unsigned al0 = __float_as_uint(af[mt][0].y);
                        unsigned al1 = __float_as_uint(af[mt][1].y);
                        unsigned al2 = __float_as_uint(af[mt][2].y);
                        unsigned al3 = __float_as_uint(af[mt][3].y);
                        float4& d = acc[it][mt][nt];
                        mma_tf32(d, ah0, ah1, ah2, ah3, bh0, bh1);
                        mma_tf32(d, ah0, ah1, ah2, ah3, bl0, bl1);
                        mma_tf32(d, al0, al1, al2, al3, bh0, bh1);
                    }
                }
            }
        }
        __syncthreads();
    }
    #pragma unroll
    for (int it=0; it<2; it++){
        float* C = it ? g_Ce1 : g_Ce0;
        #pragma unroll
        for (int mt=0; mt<2; mt++){
            #pragma unroll
            for (int nt=0; nt<2; nt++){
                float4 d = acc[it][mt][nt];
                int rl0 = mw*32 + mt*16 + g;
                int col = n0 + nw*16 + nt*8 + ctg*2;
                if (m0 + rl0 < cnt){
                    float* p = C + pp[rl0]*HD + col;
                    p[0] = d.x; p[1] = d.y;
                }
                int rl1 = rl0 + 8;
                if (m0 + rl1 < cnt){
                    float* p = C + pp[rl1]*HD + col;
                    p[0] = d.z; p[1] = d.w;
                }
            }
        }
    }
}

// ---------------- message pass + scatter-sum. grid 100, 512 thr, 4-deep prefetch ----------------
__global__ void k_msg(int it, const float* __restrict__ lgg,
                      const float* __restrict__ Wt, const float* __restrict__ bne){
    __shared__ float lg[400];
    __shared__ int   jl[100];
    __shared__ int   njl;
    const float* childin  = it ? g_child1 : g_child0;
    float*       childout = it ? g_child2 : g_child1;
    const float* Ce       = it ? g_Ce1    : g_Ce0;
    const int i = blockIdx.x, h = threadIdx.x;
    if (h < 400) lg[h] = lgg[i*400 + h];
    __syncthreads();
    if (h == 0){
        int n = 0;
        if (g_nodeok[i]){
            for (int j=0; j<MD; j++){
                if (!g_nodeok[j]) continue;
                if (lg[j*4]>0.f || lg[j*4+1]>0.f || lg[j*4+2]>0.f || lg[j*4+3]>0.f) jl[n++] = j;
            }
        }
        njl = n;
    }
    __syncthreads();
    float cin = childin[i*HD + h];
    bool any = (g_paircnt > 0);
    float acc = 0.f;
    const int n = njl;
    float base_i = g_Ai[i*HD + h] + bne[h];
    float wt0 = Wt[h], wt1 = Wt[HD+h], wt2 = Wt[2*HD+h], wt3 = Wt[3*HD+h];
    const float* CeI = Ce + (long long)i*MD*HD;

    #define MSG_BODY(JB, CB, CC) { \
        float l0 = lg[(JB)*4], l1 = lg[(JB)*4+1], l2 = lg[(JB)*4+2], l3 = lg[(JB)*4+3]; \
        float base = base_i + (CB) + (CC); \
        if (l0 > 0.f) acc += fmaxf(fmaf(l0, wt0, base), 0.f); \
        if (l1 > 0.f) acc += fmaxf(fmaf(l1, wt1, base), 0.f); \
        if (l2 > 0.f) acc += fmaxf(fmaf(l2, wt2, base), 0.f); \
        if (l3 > 0.f) acc += fmaxf(fmaf(l3, wt3, base), 0.f); }

    float b0=0,b1=0,b2=0,b3=0,c0=0,c1=0,c2=0,c3=0;
    if (n > 0){ int j=jl[0]; b0=g_Bj[j*HD+h]; c0=CeI[j*HD+h]; }
    if (n > 1){ int j=jl[1]; b1=g_Bj[j*HD+h]; c1=CeI[j*HD+h]; }
    if (n > 2){ int j=jl[2]; b2=g_Bj[j*HD+h]; c2=CeI[j*HD+h]; }
    if (n > 3){ int j=jl[3]; b3=g_Bj[j*HD+h]; c3=CeI[j*HD+h]; }
    int q = 0;
    const int nq = n & ~3;
    for (; q < nq; q += 4){
        float tb0=b0, tc0=c0, tb1=b1, tc1=c1, tb2=b2, tc2=c2, tb3=b3, tc3=c3;
        if (q+4 < n){ int j=jl[q+4]; b0=g_Bj[j*HD+h]; c0=CeI[j*HD+h]; }
        if (q+5 < n){ int j=jl[q+5]; b1=g_Bj[j*HD+h]; c1=CeI[j*HD+h]; }
        if (q+6 < n){ int j=jl[q+6]; b2=g_Bj[j*HD+h]; c2=CeI[j*HD+h]; }
        if (q+7 < n){ int j=jl[q+7]; b3=g_Bj[j*HD+h]; c3=CeI[j*HD+h]; }
        MSG_BODY(jl[q  ], tb0, tc0);
        MSG_BODY(jl[q+1], tb1, tc1);
        MSG_BODY(jl[q+2], tb2, tc2);
        MSG_BODY(jl[q+3], tb3, tc3);
    }
    for (; q < n; q++){
        int j = jl[q];
        float cb = g_Bj[j*HD+h], cc = CeI[j*HD+h];
        MSG_BODY(j, cb, cc);
    }
    #undef MSG_BODY
    childout[i*HD + h] = any ? acc : cin;
}

// ---------------- heads partials with inline h-reduce. grid (9,4,4) ----------------
__device__ __forceinline__ float hval(int gm, int k, const float* __restrict__ bc){
    float s = 0.f;
    #pragma unroll
    for (int z=0; z<8; z++) s += g_part[(size_t)z*MN + gm*HD + k];
    return fmaxf(s + bc[k], 0.f);
}
__global__ void k_heads(const float* __restrict__ Wc2, const float* __restrict__ Ws,
                        const float* __restrict__ bc){
    __shared__ ull   As2[16*33];
    __shared__ float Bs[16*68];
    const bool semjob = (blockIdx.x == 8);
    const float* B = semjob ? Ws : Wc2;
    const int N   = semjob ? 57 : 512;
    const int n0  = semjob ? 0  : blockIdx.x*64;
    const int m0  = blockIdx.y*32;
    const int kb  = blockIdx.z*128;
    const int t = threadIdx.x, tr = t>>4, tc = t&15;
    const int ar0 = t>>4, ak = t&15, ar1 = ar0+16;
    const int bn = t&63, bk0 = t>>6;
    const int gm0 = m0+ar0, gm1 = m0+ar1;
    const bool bok = (n0 + bn) < N;
    float pa0, pa1, pb0, pb1, pb2, pb3;
    {
        int k = kb + ak;
        pa0 = (gm0 < MD) ? hval(gm0, k, bc) : 0.f;
        pa1 = (gm1 < MD) ? hval(gm1, k, bc) : 0.f;
        int kB = kb + bk0;
        pb0 = bok ? B[(kB   )*N + n0+bn] : 0.f;
        pb1 = bok ? B[(kB+4 )*N + n0+bn] : 0.f;
        pb2 = bok ? B[(kB+8 )*N + n0+bn] : 0.f;
        pb3 = bok ? B[(kB+12)*N + n0+bn] : 0.f;
    }
    ull acc[2][2] = {};
    for (int kt=0; kt<8; kt++){
        As2[ak*33 + ar0] = dup2(pa0);
        As2[ak*33 + ar1] = dup2(pa1);
        Bs[(bk0   )*68 + bn] = pb0;
        Bs[(bk0+4 )*68 + bn] = pb1;
        Bs[(bk0+8 )*68 + bn] = pb2;
        Bs[(bk0+12)*68 + bn] = pb3;
        __syncthreads();
        if (kt+1 < 8){
            int k = kb + (kt+1)*16 + ak;
            pa0 = (gm0 < MD) ? hval(gm0, k, bc) : 0.f;
            pa1 = (gm1 < MD) ? hval(gm1, k, bc) : 0.f;
            int kB = kb + (kt+1)*16 + bk0;
            pb0 = bok ? B[(kB   )*N + n0+bn] : 0.f;
            pb1 = bok ? B[(kB+4 )*N + n0+bn] : 0.f;
            pb2 = bok ? B[(kB+8 )*N + n0+bn] : 0.f;
            pb3 = bok ? B[(kB+12)*N + n0+bn] : 0.f;
        }
        #pragma unroll
        for (int k=0; k<16; k++){
            ull a0 = As2[k*33+tr], a1 = As2[k*33+tr+16];
            float4 bf = *(const float4*)&Bs[k*68 + tc*4];
            ull b0 = ((const ull*)&bf)[0], b1 = ((const ull*)&bf)[1];
            acc[0][0]=ffma2(a0,b0,acc[0][0]); acc[0][1]=ffma2(a0,b1,acc[0][1]);
            acc[1][0]=ffma2(a1,b0,acc[1][0]); acc[1][1]=ffma2(a1,b1,acc[1][1]);
        }
        __syncthreads();
    }
    const int sl = blockIdx.z;
    #pragma unroll
    for (int rr=0; rr<2; rr++){
        int gm = m0 + tr + rr*16;
        if (gm >= MD) continue;
        float r0 = __uint_as_float((unsigned)(acc[rr][0]      ));
        float r1 = __uint_as_float((unsigned)(acc[rr][0] >> 32));
        float r2 = __uint_as_float((unsigned)(acc[rr][1]      ));
        float r3 = __uint_as_float((unsigned)(acc[rr][1] >> 32));
        int gn = n0 + tc*4;
        if (!semjob){
            ull* cp = (ull*)(g_part + (size_t)(8+sl)*MN + gm*HD + gn);
            cp[0] = acc[rr][0]; cp[1] = acc[rr][1];
        } else {
            float* P = g_partS + sl*5700 + gm*57;
            if (gn   < 57) P[gn  ] = r0;
            if (gn+1 < 57) P[gn+1] = r1;
            if (gn+2 < 57) P[gn+2] = r2;
            if (gn+3 < 57) P[gn+3] = r3;
        }
    }
}

// final output reduce. blocks 0..49: child_out float4 (part slices 8..11), 50..72: sem scalar.
__global__ void k_out(const float* __restrict__ bc2, const float* __restrict__ bs,
                      float* __restrict__ out_co, float* __restrict__ out_sem){
    if (blockIdx.x < 50){
        int i4 = blockIdx.x*256 + threadIdx.x;
        const float4* P = (const float4*)g_part;
        float4 s = make_float4(0.f,0.f,0.f,0.f);
        #pragma unroll
        for (int z=0; z<4; z++){
            float4 v = P[(size_t)(8+z)*12800 + i4];
            s.x+=v.x; s.y+=v.y; s.z+=v.z; s.w+=v.w;
        }
        float4 b = ((const float4*)bc2)[i4 & 127];
        s.x = fmaxf(s.x+b.x,0.f); s.y = fmaxf(s.y+b.y,0.f);
        s.z = fmaxf(s.z+b.z,0.f); s.w = fmaxf(s.w+b.w,0.f);
        ((float4*)out_co)[i4] = s;
    } else {
        int e = (blockIdx.x-50)*256 + threadIdx.x;
        if (e >= 5700) return;
        float s = 0.f;
        #pragma unroll
        for (int z=0; z<4; z++) s += g_partS[z*5700 + e];
        out_sem[e] = s + bs[e % 57];
    }
}

// ---------------- launch: 13 kernels ----------------
extern "C" void kernel_launch(void* const* d_in, const int* in_sizes, int n_in,
                              void* d_out, int out_size){
    const float* pf  = (const float*)d_in[0];
    const float* Wp  = (const float*)d_in[1];
    const float* bp  = (const float*)d_in[2];
    const float* Wx  = (const float*)d_in[3];
    const float* bx  = (const float*)d_in[4];
    const float* Wel = (const float*)d_in[5];
    const float* bel = (const float*)d_in[6];
    const float* Wee = (const float*)d_in[7];
    const float* bee = (const float*)d_in[8];
    const float* Wne = (const float*)d_in[9];
    const float* bne = (const float*)d_in[10];
    const float* Wc  = (const float*)d_in[11];
    const float* bc  = (const float*)d_in[12];
    const float* Ws  = (const float*)d_in[13];
    const float* bs  = (const float*)d_in[14];
    const float* Wc2 = (const float*)d_in[15];
    const float* bc2 = (const float*)d_in[16];

    float* out     = (float*)d_out;
    float* out_co  = out;
    float* out_sem = out + 51200;
    float* out_ex  = out + 56900;
    float* out_lg  = out + 57000;

    k_gemv_part<<<dim3(50,4),256>>>(pf, Wp);
    k_gemv_fin<<<100,128>>>(bp, Wx, bx, out_ex);
    // A_el, B_el, Ai0, Bj0 — 4 jobs fused on shared A (child0)
    k_gpf<4><<<dim3(8,4,4),256>>>(5, Wel, Wel + 512*512, Wne, Wne + 512*512);
    k_red<<<200,256>>>(4, 4, 0, 1, 2, 3);
    k_el<<<dim3(100,13),256>>>(bel, Wee, bee, out_lg);
    k_ce<<<dim3(8,157),256>>>(Wne + 1024*512, Wne + (1540+1024)*512, bel);
    k_msg<<<100,512>>>(0, out_lg, Wne + 1536*512, bne);
    // Ai1, Bj1 — 2 jobs fused on shared A (child1)
    k_gpf<2><<<dim3(8,4,4),256>>>(6, Wne + 1540*512, Wne + (1540+512)*512, Wne, Wne);
    k_red<<<100,256>>>(4, 2, 2, 3, 0, 0);
    k_msg<<<100,512>>>(1, out_lg, Wne + (1540+1536)*512, bne + 512);
    k_gp<<<dim3(8,4,8),256>>>(9, 1536, 8, Wc);
    k_heads<<<dim3(9,4,4),256>>>(Wc2, Ws, bc);
    k_out<<<73,256>>>(bc2, bs, out_co, out_sem);
}